// round 2
// baseline (speedup 1.0000x reference)
#include <cuda_runtime.h>
#include <cuda_bf16.h>

#define BQ   1024

// ---------- packed fp32x2 FMA (Blackwell FFMA2) ----------
union F2U { float2 f; unsigned long long u; };
__device__ __forceinline__ float2 ffma2(float2 a, float2 b, float2 c) {
    F2U A, B, C, D;
    A.f = a; B.f = b; C.f = c;
    asm("fma.rn.f32x2 %0, %1, %2, %3;" : "=l"(D.u) : "l"(A.u), "l"(B.u), "l"(C.u));
    return D.f;
}
__device__ __forceinline__ float2 mf2(float x, float y) { float2 r; r.x = x; r.y = y; return r; }

// Folded-weight device globals (written by precompute kernel)
__device__ float g_s[64];      // strength @ str_w + str_b
__device__ float g_AkT[512];   // [j][c] = sum_d Wk[d][c] * attn_w1[d][j]
__device__ float g_AqT[512];   // [j][c]
__device__ float g_ApT[64];    // [j][i] = sum_d pos_w2[i][d] * attn_w1[d][j]
__device__ float g_cb[8];      // [j]

__global__ void precompute_kernel(
    const float* __restrict__ strength, const float* __restrict__ str_w,
    const float* __restrict__ str_b,
    const float* __restrict__ q_tbl, const float* __restrict__ k_tbl,
    const float* __restrict__ attn_w1, const float* __restrict__ attn_b1,
    const float* __restrict__ pos_w2, const float* __restrict__ pos_b2,
    const int* __restrict__ embed_id)
{
    const int t = threadIdx.x;
    const int e = embed_id[0];

    if (t < 64) {
        float acc = str_b[t];
        for (int i = 0; i < 512; ++i) acc += strength[i] * str_w[i * 64 + t];
        g_s[t] = acc;
    }
    for (int idx = t; idx < 512; idx += 256) {
        const int j = idx >> 6, c = idx & 63;
        float ak = 0.f, aq = 0.f;
        for (int dd = 0; dd < 64; ++dd) {
            const float w1 = attn_w1[dd * 8 + j];
            ak += k_tbl[e * 4096 + dd * 64 + c] * w1;
            aq += q_tbl[e * 4096 + dd * 64 + c] * w1;
        }
        g_AkT[idx] = ak;
        g_AqT[idx] = aq;
    }
    if (t < 64) {
        const int j = t >> 3, i = t & 7;
        float ap = 0.f;
        for (int dd = 0; dd < 64; ++dd) ap += pos_w2[i * 64 + dd] * attn_w1[dd * 8 + j];
        g_ApT[j * 8 + i] = ap;
    }
    if (t < 8) {
        float cb = attn_b1[t];
        for (int dd = 0; dd < 64; ++dd) cb += pos_b2[dd] * attn_w1[dd * 8 + t];
        g_cb[t] = cb;
    }
}

__global__ __launch_bounds__(256, 2)
void attn_main(
    const float* __restrict__ q, const float* __restrict__ k,
    const float* __restrict__ pos,
    const float* __restrict__ v_tbl,
    const float* __restrict__ pos_w1, const float* __restrict__ pos_b1,
    const float* __restrict__ pos_w2, const float* __restrict__ pos_b2,
    const float* __restrict__ attn_w2, const float* __restrict__ attn_b2,
    const float* __restrict__ out_w, const float* __restrict__ out_b,
    const int* __restrict__ mask, const int* __restrict__ embed_id,
    float* __restrict__ out)
{
    __shared__ __align__(16) float s_owT[64 * 68];   // out_w transposed [d][c]
    __shared__ __align__(16) float s_k[32 * 68];     // k rows, stride 68
    __shared__ __align__(16) float s_akT[8 * 68];    // [j][c]
    __shared__ __align__(16) float s_aqT[8 * 68];    // [j][c]
    __shared__ __align__(16) float s_q[256];
    __shared__ __align__(16) float s_ph[256];        // [ln*8+v][8]
    __shared__ __align__(16) float s_hh[256];        // [ln*8+v][8]
    __shared__ __align__(16) float s_pos[128];       // [ln*8+v][4]
    __shared__ __align__(16) float s_apT[64];        // [j][i]
    __shared__ float s_x[256];
    __shared__ float s_h1q[32];
    __shared__ float s_pw1[32];
    __shared__ int   s_mask[32];
    __shared__ int   s_mbits[4];

    const int tid = threadIdx.x;
    const int b = blockIdx.x;
    const int nbase = blockIdx.y * 32;
    const int e = embed_id[0];

    // ---- one-time per-block shared staging ----
    for (int i = tid; i < 4096; i += 256) {
        const int c = i >> 6, dd = i & 63;
        s_owT[dd * 68 + c] = out_w[i];
    }
    for (int i = tid; i < 512; i += 256) {
        const int jj = i >> 6, c = i & 63;
        s_akT[jj * 68 + c] = g_AkT[i];
        s_aqT[jj * 68 + c] = g_AqT[i];
    }
    if (tid < 64) s_apT[tid] = g_ApT[tid];
    if (tid < 32) s_pw1[tid] = pos_w1[tid];

    const int d  = tid & 63;
    const int j  = tid & 7;
    const int vA = (tid >> 3) & 7;
    const int ln = tid >> 6;

    // ---- per-thread register weights ----
    float2 wv2[32];
    {
        const float* wvg = v_tbl + e * 4096 + d * 64;
        #pragma unroll
        for (int c4 = 0; c4 < 16; ++c4) {
            const float4 t4 = *reinterpret_cast<const float4*>(wvg + 4 * c4);
            wv2[2 * c4]     = mf2(t4.x, t4.y);
            wv2[2 * c4 + 1] = mf2(t4.z, t4.w);
        }
    }
    float2 aw2r[4], pw2r[4];
    #pragma unroll
    for (int p = 0; p < 4; ++p) {
        aw2r[p] = mf2(attn_w2[(2 * p) * 64 + d], attn_w2[(2 * p + 1) * 64 + d]);
        pw2r[p] = mf2(pos_w2[(2 * p) * 64 + d], pos_w2[(2 * p + 1) * 64 + d]);
    }
    const float sd   = g_s[d];
    const float ab2d = attn_b2[d];
    const float obd  = out_b[d];
    const float pb2d = pos_b2[d];
    const float cbj  = g_cb[j];
    const float pb1j = pos_b1[j];

    __syncthreads();

    const int ln8v = ln * 8 + vA;

    for (int chunk = 0; chunk < 8; ++chunk) {
        const int n0 = nbase + chunk * 4;
        const long base_n = (long)b * 64 + n0;

        // ---- cooperative loads ----
        s_q[tid] = q[base_n * 64 + tid];
        {
            const float4* kg = reinterpret_cast<const float4*>(k + base_n * 512);
            #pragma unroll
            for (int r = 0; r < 2; ++r) {
                const int i = tid + 256 * r;
                const int row = i >> 4, c4 = i & 15;
                reinterpret_cast<float4*>(s_k + row * 68)[c4] = kg[i];
            }
        }
        if (tid < 128) s_pos[tid] = pos[base_n * 32 + tid];
        if (tid < 32)  s_mask[tid] = mask[base_n * 8 + tid];
        __syncthreads();

        // ---- phase A1: pos-MLP hidden + q-fold + mask pack ----
        {
            const float4 p4 = *reinterpret_cast<const float4*>(s_pos + ln8v * 4);
            float acc = pb1j;
            acc += p4.x * s_pw1[0 * 8 + j];
            acc += p4.y * s_pw1[1 * 8 + j];
            acc += p4.z * s_pw1[2 * 8 + j];
            acc += p4.w * s_pw1[3 * 8 + j];
            s_ph[ln8v * 8 + j] = fmaxf(acc, 0.f);
        }
        if (vA == 0) {
            float2 a = mf2(0.f, 0.f);
            const float4* qr = reinterpret_cast<const float4*>(s_q + ln * 64);
            const float4* ar = reinterpret_cast<const float4*>(s_aqT + j * 68);
            #pragma unroll
            for (int c4 = 0; c4 < 16; ++c4) {
                const float4 qq = qr[c4], aa = ar[c4];
                a = ffma2(mf2(qq.x, qq.y), mf2(aa.x, aa.y), a);
                a = ffma2(mf2(qq.z, qq.w), mf2(aa.z, aa.w), a);
            }
            s_h1q[ln * 8 + j] = a.x + a.y;
        }
        if (tid < 4) {
            int bits = 0;
            #pragma unroll
            for (int v = 0; v < 8; ++v) bits |= (s_mask[tid * 8 + v] != 0) << v;
            s_mbits[tid] = bits;
        }
        __syncthreads();

        // ---- phase A2: attn hidden (folded) ----
        {
            float2 acc = mf2(cbj - s_h1q[ln * 8 + j], 0.f);
            const float4* kr = reinterpret_cast<const float4*>(s_k + ln8v * 68);
            const float4* ar = reinterpret_cast<const float4*>(s_akT + j * 68);
            #pragma unroll
            for (int c4 = 0; c4 < 16; ++c4) {
                const float4 kk = kr[c4], aa = ar[c4];
                acc = ffma2(mf2(kk.x, kk.y), mf2(aa.x, aa.y), acc);
                acc = ffma2(mf2(kk.z, kk.w), mf2(aa.z, aa.w), acc);
            }
            const float4* phr = reinterpret_cast<const float4*>(s_ph + ln8v * 8);
            const float4  h0 = phr[0], h1 = phr[1];
            const float4* apr = reinterpret_cast<const float4*>(s_apT + j * 8);
            const float4  a0 = apr[0], a1 = apr[1];
            acc = ffma2(mf2(h0.x, h0.y), mf2(a0.x, a0.y), acc);
            acc = ffma2(mf2(h0.z, h0.w), mf2(a0.z, a0.w), acc);
            acc = ffma2(mf2(h1.x, h1.y), mf2(a1.x, a1.y), acc);
            acc = ffma2(mf2(h1.z, h1.w), mf2(a1.z, a1.w), acc);
            s_hh[ln8v * 8 + j] = fmaxf(acc.x + acc.y, 0.f);
        }
        __syncthreads();

        // ---- phase B: logits + vh + p, online softmax over V ----
        {
            const int mbits = s_mbits[ln];
            float m = -1e30f, ssum = 0.f, wacc = 0.f;
            #pragma unroll
            for (int v = 0; v < 8; ++v) {
                const int row = ln * 8 + v;
                const float4* hhr = reinterpret_cast<const float4*>(s_hh + row * 8);
                const float4 h0 = hhr[0], h1 = hhr[1];
                float2 a2 = ffma2(mf2(h0.x, h0.y), aw2r[0], mf2(ab2d, 0.f));
                a2 = ffma2(mf2(h0.z, h0.w), aw2r[1], a2);
                a2 = ffma2(mf2(h1.x, h1.y), aw2r[2], a2);
                a2 = ffma2(mf2(h1.z, h1.w), aw2r[3], a2);

                const float4* phr = reinterpret_cast<const float4*>(s_ph + row * 8);
                const float4 p0 = phr[0], p1 = phr[1];
                float2 pv = ffma2(mf2(p0.x, p0.y), pw2r[0], mf2(pb2d, 0.f));
                pv = ffma2(mf2(p0.z, p0.w), pw2r[1], pv);
                pv = ffma2(mf2(p1.x, p1.y), pw2r[2], pv);
                pv = ffma2(mf2(p1.z, p1.w), pw2r[3], pv);

                float2 vh2 = mf2(sd, 0.f);
                const float4* kr4 = reinterpret_cast<const float4*>(s_k + row * 68);
                #pragma unroll
                for (int c4 = 0; c4 < 16; ++c4) {
                    const float4 kk = kr4[c4];
                    vh2 = ffma2(mf2(kk.x, kk.y), wv2[2 * c4], vh2);
                    vh2 = ffma2(mf2(kk.z, kk.w), wv2[2 * c4 + 1], vh2);
                }
                const float logit = ((mbits >> v) & 1) ? (a2.x + a2.y) : -1e9f;
                const float val = vh2.x + vh2.y + pv.x + pv.y;
                const float nm = fmaxf(m, logit);
                const float scale = __expf(m - nm);
                const float ev = __expf(logit - nm);
                ssum = ssum * scale + ev;
                wacc = wacc * scale + ev * val;
                m = nm;
            }
            s_x[ln * 64 + d] = __fdividef(wacc, ssum);
        }
        __syncthreads();

        // ---- output GEMM: y = x @ out_w + out_b ----
        {
            float2 y2 = mf2(obd, 0.f);
            const float4* xr = reinterpret_cast<const float4*>(s_x + ln * 64);
            const float4* wr = reinterpret_cast<const float4*>(s_owT + d * 68);
            #pragma unroll
            for (int c4 = 0; c4 < 16; ++c4) {
                const float4 xx = xr[c4], ww = wr[c4];
                y2 = ffma2(mf2(xx.x, xx.y), mf2(ww.x, ww.y), y2);
                y2 = ffma2(mf2(xx.z, xx.w), mf2(ww.z, ww.w), y2);
            }
            out[(base_n + ln) * 64 + d] = y2.x + y2.y;
        }
        __syncthreads();
    }
}

extern "C" void kernel_launch(void* const* d_in, const int* in_sizes, int n_in,
                              void* d_out, int out_size)
{
    const float* q        = (const float*)d_in[0];
    const float* k        = (const float*)d_in[1];
    const float* pos      = (const float*)d_in[2];
    const float* strength = (const float*)d_in[3];
    const float* q_tbl    = (const float*)d_in[4];
    const float* k_tbl    = (const float*)d_in[5];
    const float* v_tbl    = (const float*)d_in[6];
    const float* pos_w1   = (const float*)d_in[7];
    const float* pos_b1   = (const float*)d_in[8];
    const float* pos_w2   = (const float*)d_in[9];
    const float* pos_b2   = (const float*)d_in[10];
    const float* attn_w1  = (const float*)d_in[11];
    const float* attn_b1  = (const float*)d_in[12];
    const float* attn_w2  = (const float*)d_in[13];
    const float* attn_b2  = (const float*)d_in[14];
    const float* out_w    = (const float*)d_in[15];
    const float* out_b    = (const float*)d_in[16];
    const float* str_w    = (const float*)d_in[17];
    const float* str_b    = (const float*)d_in[18];
    const int*   mask     = (const int*)d_in[19];
    const int*   embed_id = (const int*)d_in[20];
    float* out = (float*)d_out;

    precompute_kernel<<<1, 256>>>(strength, str_w, str_b, q_tbl, k_tbl,
                                  attn_w1, attn_b1, pos_w2, pos_b2, embed_id);

    dim3 grid(BQ, 2);
    attn_main<<<grid, 256>>>(q, k, pos, v_tbl,
                             pos_w1, pos_b1, pos_w2, pos_b2,
                             attn_w2, attn_b2, out_w, out_b,
                             mask, embed_id, out);
}

// round 3
// speedup vs baseline: 1.0012x; 1.0012x over previous
#include <cuda_runtime.h>
#include <cuda_bf16.h>

#define BQ   1024

// ---------- packed fp32x2 FMA (Blackwell FFMA2) ----------
union F2U { float2 f; unsigned long long u; };
__device__ __forceinline__ float2 ffma2(float2 a, float2 b, float2 c) {
    F2U A, B, C, D;
    A.f = a; B.f = b; C.f = c;
    asm("fma.rn.f32x2 %0, %1, %2, %3;" : "=l"(D.u) : "l"(A.u), "l"(B.u), "l"(C.u));
    return D.f;
}
__device__ __forceinline__ float2 mf2(float x, float y) { float2 r; r.x = x; r.y = y; return r; }

// Folded-weight device globals (written by precompute kernel)
__device__ float g_s[64];      // strength @ str_w + str_b
__device__ float g_AkT[512];   // [j][c] = sum_d Wk[d][c] * attn_w1[d][j]
__device__ float g_AqT[512];   // [j][c]
__device__ float g_ApT[64];    // [j][i] = sum_d pos_w2[i][d] * attn_w1[d][j]
__device__ float g_cb[8];      // [j]

__global__ void precompute_kernel(
    const float* __restrict__ strength, const float* __restrict__ str_w,
    const float* __restrict__ str_b,
    const float* __restrict__ q_tbl, const float* __restrict__ k_tbl,
    const float* __restrict__ attn_w1, const float* __restrict__ attn_b1,
    const float* __restrict__ pos_w2, const float* __restrict__ pos_b2,
    const int* __restrict__ embed_id)
{
    const int t = threadIdx.x;
    const int e = embed_id[0];

    if (t < 64) {
        float acc = str_b[t];
        for (int i = 0; i < 512; ++i) acc += strength[i] * str_w[i * 64 + t];
        g_s[t] = acc;
    }
    for (int idx = t; idx < 512; idx += 256) {
        const int j = idx >> 6, c = idx & 63;
        float ak = 0.f, aq = 0.f;
        for (int dd = 0; dd < 64; ++dd) {
            const float w1 = attn_w1[dd * 8 + j];
            ak += k_tbl[e * 4096 + dd * 64 + c] * w1;
            aq += q_tbl[e * 4096 + dd * 64 + c] * w1;
        }
        g_AkT[idx] = ak;
        g_AqT[idx] = aq;
    }
    if (t < 64) {
        const int j = t >> 3, i = t & 7;
        float ap = 0.f;
        for (int dd = 0; dd < 64; ++dd) ap += pos_w2[i * 64 + dd] * attn_w1[dd * 8 + j];
        g_ApT[j * 8 + i] = ap;
    }
    if (t < 8) {
        float cb = attn_b1[t];
        for (int dd = 0; dd < 64; ++dd) cb += pos_b2[dd] * attn_w1[dd * 8 + t];
        g_cb[t] = cb;
    }
}

__global__ __launch_bounds__(256, 2)
void attn_main(
    const float* __restrict__ q, const float* __restrict__ k,
    const float* __restrict__ pos,
    const float* __restrict__ v_tbl,
    const float* __restrict__ pos_w1, const float* __restrict__ pos_b1,
    const float* __restrict__ pos_w2, const float* __restrict__ pos_b2,
    const float* __restrict__ attn_w2, const float* __restrict__ attn_b2,
    const float* __restrict__ out_w, const float* __restrict__ out_b,
    const int* __restrict__ mask, const int* __restrict__ embed_id,
    float* __restrict__ out)
{
    __shared__ __align__(16) float s_owT[64 * 68];   // out_w transposed [d][c]
    __shared__ __align__(16) float s_k[32 * 68];     // k rows, stride 68
    __shared__ __align__(16) float s_akT[8 * 68];    // [j][c]
    __shared__ __align__(16) float s_aqT[8 * 68];    // [j][c]
    __shared__ __align__(16) float s_q[256];
    __shared__ __align__(16) float s_ph[256];        // [ln*8+v][8]
    __shared__ __align__(16) float s_hh[256];        // [ln*8+v][8]
    __shared__ __align__(16) float s_pos[128];       // [ln*8+v][4]
    __shared__ __align__(16) float s_apT[64];        // [j][i]
    __shared__ float s_x[256];
    __shared__ float s_h1q[32];
    __shared__ float s_pw1[32];
    __shared__ int   s_mask[32];
    __shared__ int   s_mbits[4];

    const int tid = threadIdx.x;
    const int b = blockIdx.x;
    const int nbase = blockIdx.y * 32;
    const int e = embed_id[0];

    // ---- one-time per-block shared staging ----
    for (int i = tid; i < 4096; i += 256) {
        const int c = i >> 6, dd = i & 63;
        s_owT[dd * 68 + c] = out_w[i];
    }
    for (int i = tid; i < 512; i += 256) {
        const int jj = i >> 6, c = i & 63;
        s_akT[jj * 68 + c] = g_AkT[i];
        s_aqT[jj * 68 + c] = g_AqT[i];
    }
    if (tid < 64) s_apT[tid] = g_ApT[tid];
    if (tid < 32) s_pw1[tid] = pos_w1[tid];

    const int d  = tid & 63;
    const int j  = tid & 7;
    const int vA = (tid >> 3) & 7;
    const int ln = tid >> 6;

    // ---- per-thread register weights ----
    float2 wv2[32];
    {
        const float* wvg = v_tbl + e * 4096 + d * 64;
        #pragma unroll
        for (int c4 = 0; c4 < 16; ++c4) {
            const float4 t4 = *reinterpret_cast<const float4*>(wvg + 4 * c4);
            wv2[2 * c4]     = mf2(t4.x, t4.y);
            wv2[2 * c4 + 1] = mf2(t4.z, t4.w);
        }
    }
    float2 aw2r[4], pw2r[4];
    #pragma unroll
    for (int p = 0; p < 4; ++p) {
        aw2r[p] = mf2(attn_w2[(2 * p) * 64 + d], attn_w2[(2 * p + 1) * 64 + d]);
        pw2r[p] = mf2(pos_w2[(2 * p) * 64 + d], pos_w2[(2 * p + 1) * 64 + d]);
    }
    const float sd   = g_s[d];
    const float ab2d = attn_b2[d];
    const float obd  = out_b[d];
    const float pb2d = pos_b2[d];
    const float cbj  = g_cb[j];
    const float pb1j = pos_b1[j];

    __syncthreads();

    const int ln8v = ln * 8 + vA;

    for (int chunk = 0; chunk < 8; ++chunk) {
        const int n0 = nbase + chunk * 4;
        const long base_n = (long)b * 64 + n0;

        // ---- cooperative loads ----
        s_q[tid] = q[base_n * 64 + tid];
        {
            const float4* kg = reinterpret_cast<const float4*>(k + base_n * 512);
            #pragma unroll
            for (int r = 0; r < 2; ++r) {
                const int i = tid + 256 * r;
                const int row = i >> 4, c4 = i & 15;
                reinterpret_cast<float4*>(s_k + row * 68)[c4] = kg[i];
            }
        }
        if (tid < 128) s_pos[tid] = pos[base_n * 32 + tid];
        if (tid < 32)  s_mask[tid] = mask[base_n * 8 + tid];
        __syncthreads();

        // ---- phase A1: pos-MLP hidden + q-fold + mask pack ----
        {
            const float4 p4 = *reinterpret_cast<const float4*>(s_pos + ln8v * 4);
            float acc = pb1j;
            acc += p4.x * s_pw1[0 * 8 + j];
            acc += p4.y * s_pw1[1 * 8 + j];
            acc += p4.z * s_pw1[2 * 8 + j];
            acc += p4.w * s_pw1[3 * 8 + j];
            s_ph[ln8v * 8 + j] = fmaxf(acc, 0.f);
        }
        if (vA == 0) {
            float2 a = mf2(0.f, 0.f);
            const float4* qr = reinterpret_cast<const float4*>(s_q + ln * 64);
            const float4* ar = reinterpret_cast<const float4*>(s_aqT + j * 68);
            #pragma unroll
            for (int c4 = 0; c4 < 16; ++c4) {
                const float4 qq = qr[c4], aa = ar[c4];
                a = ffma2(mf2(qq.x, qq.y), mf2(aa.x, aa.y), a);
                a = ffma2(mf2(qq.z, qq.w), mf2(aa.z, aa.w), a);
            }
            s_h1q[ln * 8 + j] = a.x + a.y;
        }
        if (tid < 4) {
            int bits = 0;
            #pragma unroll
            for (int v = 0; v < 8; ++v) bits |= (s_mask[tid * 8 + v] != 0) << v;
            s_mbits[tid] = bits;
        }
        __syncthreads();

        // ---- phase A2: attn hidden (folded) ----
        {
            float2 acc = mf2(cbj - s_h1q[ln * 8 + j], 0.f);
            const float4* kr = reinterpret_cast<const float4*>(s_k + ln8v * 68);
            const float4* ar = reinterpret_cast<const float4*>(s_akT + j * 68);
            #pragma unroll
            for (int c4 = 0; c4 < 16; ++c4) {
                const float4 kk = kr[c4], aa = ar[c4];
                acc = ffma2(mf2(kk.x, kk.y), mf2(aa.x, aa.y), acc);
                acc = ffma2(mf2(kk.z, kk.w), mf2(aa.z, aa.w), acc);
            }
            const float4* phr = reinterpret_cast<const float4*>(s_ph + ln8v * 8);
            const float4  h0 = phr[0], h1 = phr[1];
            const float4* apr = reinterpret_cast<const float4*>(s_apT + j * 8);
            const float4  a0 = apr[0], a1 = apr[1];
            acc = ffma2(mf2(h0.x, h0.y), mf2(a0.x, a0.y), acc);
            acc = ffma2(mf2(h0.z, h0.w), mf2(a0.z, a0.w), acc);
            acc = ffma2(mf2(h1.x, h1.y), mf2(a1.x, a1.y), acc);
            acc = ffma2(mf2(h1.z, h1.w), mf2(a1.z, a1.w), acc);
            s_hh[ln8v * 8 + j] = fmaxf(acc.x + acc.y, 0.f);
        }
        __syncthreads();

        // ---- phase B: logits + vh + p, online softmax over V ----
        {
            const int mbits = s_mbits[ln];
            float m = -1e30f, ssum = 0.f, wacc = 0.f;
            #pragma unroll
            for (int v = 0; v < 8; ++v) {
                const int row = ln * 8 + v;
                const float4* hhr = reinterpret_cast<const float4*>(s_hh + row * 8);
                const float4 h0 = hhr[0], h1 = hhr[1];
                float2 a2 = ffma2(mf2(h0.x, h0.y), aw2r[0], mf2(ab2d, 0.f));
                a2 = ffma2(mf2(h0.z, h0.w), aw2r[1], a2);
                a2 = ffma2(mf2(h1.x, h1.y), aw2r[2], a2);
                a2 = ffma2(mf2(h1.z, h1.w), aw2r[3], a2);

                const float4* phr = reinterpret_cast<const float4*>(s_ph + row * 8);
                const float4 p0 = phr[0], p1 = phr[1];
                float2 pv = ffma2(mf2(p0.x, p0.y), pw2r[0], mf2(pb2d, 0.f));
                pv = ffma2(mf2(p0.z, p0.w), pw2r[1], pv);
                pv = ffma2(mf2(p1.x, p1.y), pw2r[2], pv);
                pv = ffma2(mf2(p1.z, p1.w), pw2r[3], pv);

                float2 vh2 = mf2(sd, 0.f);
                const float4* kr4 = reinterpret_cast<const float4*>(s_k + row * 68);
                #pragma unroll
                for (int c4 = 0; c4 < 16; ++c4) {
                    const float4 kk = kr4[c4];
                    vh2 = ffma2(mf2(kk.x, kk.y), wv2[2 * c4], vh2);
                    vh2 = ffma2(mf2(kk.z, kk.w), wv2[2 * c4 + 1], vh2);
                }
                const float logit = ((mbits >> v) & 1) ? (a2.x + a2.y) : -1e9f;
                const float val = vh2.x + vh2.y + pv.x + pv.y;
                const float nm = fmaxf(m, logit);
                const float scale = __expf(m - nm);
                const float ev = __expf(logit - nm);
                ssum = ssum * scale + ev;
                wacc = wacc * scale + ev * val;
                m = nm;
            }
            s_x[ln * 64 + d] = __fdividef(wacc, ssum);
        }
        __syncthreads();

        // ---- output GEMM: y = x @ out_w + out_b ----
        {
            float2 y2 = mf2(obd, 0.f);
            const float4* xr = reinterpret_cast<const float4*>(s_x + ln * 64);
            const float4* wr = reinterpret_cast<const float4*>(s_owT + d * 68);
            #pragma unroll
            for (int c4 = 0; c4 < 16; ++c4) {
                const float4 xx = xr[c4], ww = wr[c4];
                y2 = ffma2(mf2(xx.x, xx.y), mf2(ww.x, ww.y), y2);
                y2 = ffma2(mf2(xx.z, xx.w), mf2(ww.z, ww.w), y2);
            }
            out[(base_n + ln) * 64 + d] = y2.x + y2.y;
        }
        __syncthreads();
    }
}

extern "C" void kernel_launch(void* const* d_in, const int* in_sizes, int n_in,
                              void* d_out, int out_size)
{
    const float* q        = (const float*)d_in[0];
    const float* k        = (const float*)d_in[1];
    const float* pos      = (const float*)d_in[2];
    const float* strength = (const float*)d_in[3];
    const float* q_tbl    = (const float*)d_in[4];
    const float* k_tbl    = (const float*)d_in[5];
    const float* v_tbl    = (const float*)d_in[6];
    const float* pos_w1   = (const float*)d_in[7];
    const float* pos_b1   = (const float*)d_in[8];
    const float* pos_w2   = (const float*)d_in[9];
    const float* pos_b2   = (const float*)d_in[10];
    const float* attn_w1  = (const float*)d_in[11];
    const float* attn_b1  = (const float*)d_in[12];
    const float* attn_w2  = (const float*)d_in[13];
    const float* attn_b2  = (const float*)d_in[14];
    const float* out_w    = (const float*)d_in[15];
    const float* out_b    = (const float*)d_in[16];
    const float* str_w    = (const float*)d_in[17];
    const float* str_b    = (const float*)d_in[18];
    const int*   mask     = (const int*)d_in[19];
    const int*   embed_id = (const int*)d_in[20];
    float* out = (float*)d_out;

    precompute_kernel<<<1, 256>>>(strength, str_w, str_b, q_tbl, k_tbl,
                                  attn_w1, attn_b1, pos_w2, pos_b2, embed_id);

    dim3 grid(BQ, 2);
    attn_main<<<grid, 256>>>(q, k, pos, v_tbl,
                             pos_w1, pos_b1, pos_w2, pos_b2,
                             attn_w2, attn_b2, out_w, out_b,
                             mask, embed_id, out);
}

// round 4
// speedup vs baseline: 1.0670x; 1.0657x over previous
#include <cuda_runtime.h>
#include <cuda_bf16.h>

#define BQ 1024

// ---------- packed fp32x2 FMA (Blackwell FFMA2) ----------
union F2U { float2 f; unsigned long long u; };
__device__ __forceinline__ float2 ffma2(float2 a, float2 b, float2 c) {
    F2U A, B, C, D;
    A.f = a; B.f = b; C.f = c;
    asm("fma.rn.f32x2 %0, %1, %2, %3;" : "=l"(D.u) : "l"(A.u), "l"(B.u), "l"(C.u));
    return D.f;
}
__device__ __forceinline__ float2 mf2(float x, float y) { float2 r; r.x = x; r.y = y; return r; }

// ---------- cp.async helpers ----------
__device__ __forceinline__ unsigned su32(const void* p) {
    return (unsigned)__cvta_generic_to_shared(p);
}
#define CP16(dst_u32, src_ptr) \
    asm volatile("cp.async.cg.shared.global [%0], [%1], 16;\n" :: "r"(dst_u32), "l"(src_ptr))
#define CPCOMMIT() asm volatile("cp.async.commit_group;\n" ::: "memory")
#define CPWAIT0()  asm volatile("cp.async.wait_group 0;\n" ::: "memory")

// Folded-weight device globals
__device__ float g_s[64];      // strength @ str_w + str_b
__device__ float g_AkT[512];   // [j][c] = sum_d Wk[d][c] * attn_w1[d][j]
__device__ float g_AqT[512];   // [j][c]
__device__ float g_ApT[64];    // [j][i] = sum_d pos_w2[i][d] * attn_w1[d][j]
__device__ float g_cb[8];      // [j]

__global__ void precompute_kernel(
    const float* __restrict__ strength, const float* __restrict__ str_w,
    const float* __restrict__ str_b,
    const float* __restrict__ q_tbl, const float* __restrict__ k_tbl,
    const float* __restrict__ attn_w1, const float* __restrict__ attn_b1,
    const float* __restrict__ pos_w2, const float* __restrict__ pos_b2,
    const int* __restrict__ embed_id)
{
    const int t = threadIdx.x;
    const int e = embed_id[0];

    if (t < 64) {
        float acc = str_b[t];
        for (int i = 0; i < 512; ++i) acc += strength[i] * str_w[i * 64 + t];
        g_s[t] = acc;
    }
    for (int idx = t; idx < 512; idx += 256) {
        const int j = idx >> 6, c = idx & 63;
        float ak = 0.f, aq = 0.f;
        for (int dd = 0; dd < 64; ++dd) {
            const float w1 = attn_w1[dd * 8 + j];
            ak += k_tbl[e * 4096 + dd * 64 + c] * w1;
            aq += q_tbl[e * 4096 + dd * 64 + c] * w1;
        }
        g_AkT[idx] = ak;
        g_AqT[idx] = aq;
    }
    if (t < 64) {
        const int j = t >> 3, i = t & 7;
        float ap = 0.f;
        for (int dd = 0; dd < 64; ++dd) ap += pos_w2[i * 64 + dd] * attn_w1[dd * 8 + j];
        g_ApT[j * 8 + i] = ap;
    }
    if (t < 8) {
        float cb = attn_b1[t];
        for (int dd = 0; dd < 64; ++dd) cb += pos_b2[dd] * attn_w1[dd * 8 + t];
        g_cb[t] = cb;
    }
}

__global__ __launch_bounds__(256, 2)
void attn_main(
    const float* __restrict__ q, const float* __restrict__ k,
    const float* __restrict__ pos,
    const float* __restrict__ v_tbl,
    const float* __restrict__ pos_w1, const float* __restrict__ pos_b1,
    const float* __restrict__ pos_w2, const float* __restrict__ pos_b2,
    const float* __restrict__ attn_w2, const float* __restrict__ attn_b2,
    const float* __restrict__ out_w, const float* __restrict__ out_b,
    const int* __restrict__ mask, const int* __restrict__ embed_id,
    float* __restrict__ out)
{
    __shared__ float s_ow[4096];                         // out_w [c][d] (conflict-free for d=lane)
    __shared__ __align__(16) float s_k[2][32 * 68];      // double-buffered k rows (stride 68)
    __shared__ __align__(16) float s_akT[8 * 68];        // [j][c]
    __shared__ __align__(16) float s_aqT[8 * 68];        // [j][c]
    __shared__ __align__(16) float s_q[2][256];
    __shared__ __align__(16) float s_pos[2][128];
    __shared__ __align__(16) int   s_mask[2][32];
    __shared__ __align__(16) float s_ph[256];            // [ln*8+v][8]
    __shared__ __align__(16) float s_hh[256];            // [ln*8+v][8]
    __shared__ __align__(16) float s_apT[64];            // [j][i]
    __shared__ float s_x[256];
    __shared__ float s_h1q[32];
    __shared__ float s_pw1[32];
    __shared__ int   s_mbits[4];

    const int tid = threadIdx.x;
    const int b = blockIdx.x;
    const int nbase = blockIdx.y * 32;
    const int e = embed_id[0];

    // ---- issue chunk 0 loads FIRST (hide under weight staging) ----
    {
        const long base_n = (long)b * 64 + nbase;
        const float4* kg = (const float4*)(k + base_n * 512);
        int i = tid;
        CP16(su32(&s_k[0][(i >> 4) * 68 + (i & 15) * 4]), kg + i);
        i = tid + 256;
        CP16(su32(&s_k[0][(i >> 4) * 68 + (i & 15) * 4]), kg + i);
        if (tid < 64) CP16(su32(&s_q[0][tid * 4]),   (const float4*)(q + base_n * 64) + tid);
        if (tid < 32) CP16(su32(&s_pos[0][tid * 4]), (const float4*)(pos + base_n * 32) + tid);
        if (tid < 8)  CP16(su32(&s_mask[0][tid * 4]), (const int4*)(mask + base_n * 8) + tid);
        CPCOMMIT();
    }

    // ---- one-time per-block weight staging ----
    for (int i = tid; i < 4096; i += 256) s_ow[i] = out_w[i];   // [c][d]
    for (int i = tid; i < 512; i += 256) {
        const int jj = i >> 6, c = i & 63;
        s_akT[jj * 68 + c] = g_AkT[i];
        s_aqT[jj * 68 + c] = g_AqT[i];
    }
    if (tid < 64) s_apT[tid] = g_ApT[tid];
    if (tid < 32) s_pw1[tid] = pos_w1[tid];

    const int d  = tid & 63;
    const int j  = tid & 7;
    const int vA = (tid >> 3) & 7;
    const int ln = tid >> 6;
    const int ln8v = ln * 8 + vA;

    // ---- per-thread register weights ----
    float2 wv2[32];
    {
        const float* wvg = v_tbl + e * 4096 + d * 64;
        #pragma unroll
        for (int c4 = 0; c4 < 16; ++c4) {
            const float4 t4 = *reinterpret_cast<const float4*>(wvg + 4 * c4);
            wv2[2 * c4]     = mf2(t4.x, t4.y);
            wv2[2 * c4 + 1] = mf2(t4.z, t4.w);
        }
    }
    float2 aw2r[4], pw2r[4];
    #pragma unroll
    for (int p = 0; p < 4; ++p) {
        aw2r[p] = mf2(attn_w2[(2 * p) * 64 + d], attn_w2[(2 * p + 1) * 64 + d]);
        pw2r[p] = mf2(pos_w2[(2 * p) * 64 + d], pos_w2[(2 * p + 1) * 64 + d]);
    }
    const float sd   = g_s[d];
    const float ab2d = attn_b2[d];
    const float obd  = out_b[d];
    const float pb2d = pos_b2[d];
    const float cbj  = g_cb[j];
    const float pb1j = pos_b1[j];

    for (int chunk = 0; chunk < 8; ++chunk) {
        const int bb = chunk & 1;
        const long base_n = (long)b * 64 + nbase + chunk * 4;

        CPWAIT0();
        __syncthreads();   // buffers for this chunk visible; prior chunk's reads closed

        // ---- issue next chunk's loads (fly under this chunk's compute) ----
        if (chunk < 7) {
            const long bn1 = base_n + 4;
            const float4* kg = (const float4*)(k + bn1 * 512);
            int i = tid;
            CP16(su32(&s_k[1 - bb][(i >> 4) * 68 + (i & 15) * 4]), kg + i);
            i = tid + 256;
            CP16(su32(&s_k[1 - bb][(i >> 4) * 68 + (i & 15) * 4]), kg + i);
            if (tid < 64) CP16(su32(&s_q[1 - bb][tid * 4]),   (const float4*)(q + bn1 * 64) + tid);
            if (tid < 32) CP16(su32(&s_pos[1 - bb][tid * 4]), (const float4*)(pos + bn1 * 32) + tid);
            if (tid < 8)  CP16(su32(&s_mask[1 - bb][tid * 4]), (const int4*)(mask + bn1 * 8) + tid);
            CPCOMMIT();
        }

        // ---- phase A1: pos-MLP hidden + q-fold + mask pack ----
        {
            const float4 p4 = *reinterpret_cast<const float4*>(&s_pos[bb][ln8v * 4]);
            float acc = pb1j;
            acc += p4.x * s_pw1[0 * 8 + j];
            acc += p4.y * s_pw1[1 * 8 + j];
            acc += p4.z * s_pw1[2 * 8 + j];
            acc += p4.w * s_pw1[3 * 8 + j];
            s_ph[ln8v * 8 + j] = fmaxf(acc, 0.f);
        }
        if (vA == 0) {
            float2 a0 = mf2(0.f, 0.f), a1 = mf2(0.f, 0.f);
            const float4* qr = reinterpret_cast<const float4*>(&s_q[bb][ln * 64]);
            const float4* ar = reinterpret_cast<const float4*>(s_aqT + j * 68);
            #pragma unroll
            for (int c4 = 0; c4 < 16; ++c4) {
                const float4 qq = qr[c4], aa = ar[c4];
                a0 = ffma2(mf2(qq.x, qq.y), mf2(aa.x, aa.y), a0);
                a1 = ffma2(mf2(qq.z, qq.w), mf2(aa.z, aa.w), a1);
            }
            s_h1q[ln * 8 + j] = (a0.x + a1.x) + (a0.y + a1.y);
        }
        if (tid < 4) {
            const int4 m0 = *reinterpret_cast<const int4*>(&s_mask[bb][tid * 8]);
            const int4 m1 = *reinterpret_cast<const int4*>(&s_mask[bb][tid * 8 + 4]);
            int bits = 0;
            bits |= (m0.x != 0) << 0; bits |= (m0.y != 0) << 1;
            bits |= (m0.z != 0) << 2; bits |= (m0.w != 0) << 3;
            bits |= (m1.x != 0) << 4; bits |= (m1.y != 0) << 5;
            bits |= (m1.z != 0) << 6; bits |= (m1.w != 0) << 7;
            s_mbits[tid] = bits;
        }
        __syncthreads();

        // ---- phase A2: attn hidden (folded), 2 accumulators ----
        {
            float2 acc0 = mf2(cbj - s_h1q[ln * 8 + j], 0.f);
            float2 acc1 = mf2(0.f, 0.f);
            const float4* kr = reinterpret_cast<const float4*>(&s_k[bb][ln8v * 68]);
            const float4* ar = reinterpret_cast<const float4*>(s_akT + j * 68);
            #pragma unroll
            for (int c4 = 0; c4 < 16; ++c4) {
                const float4 kk = kr[c4], aa = ar[c4];
                acc0 = ffma2(mf2(kk.x, kk.y), mf2(aa.x, aa.y), acc0);
                acc1 = ffma2(mf2(kk.z, kk.w), mf2(aa.z, aa.w), acc1);
            }
            const float4* phr = reinterpret_cast<const float4*>(s_ph + ln8v * 8);
            const float4  h0 = phr[0], h1 = phr[1];
            const float4* apr = reinterpret_cast<const float4*>(s_apT + j * 8);
            const float4  a0 = apr[0], a1 = apr[1];
            acc0 = ffma2(mf2(h0.x, h0.y), mf2(a0.x, a0.y), acc0);
            acc1 = ffma2(mf2(h0.z, h0.w), mf2(a0.z, a0.w), acc1);
            acc0 = ffma2(mf2(h1.x, h1.y), mf2(a1.x, a1.y), acc0);
            acc1 = ffma2(mf2(h1.z, h1.w), mf2(a1.z, a1.w), acc1);
            s_hh[ln8v * 8 + j] = fmaxf((acc0.x + acc1.x) + (acc0.y + acc1.y), 0.f);
        }
        __syncthreads();

        // ---- phase B: logits + vh + p (two-pass softmax, split accumulators) ----
        {
            const int mbits = s_mbits[ln];
            float logit[8], val[8];
            #pragma unroll
            for (int v = 0; v < 8; ++v) {
                const int row = ln * 8 + v;
                const float4* hhr = reinterpret_cast<const float4*>(s_hh + row * 8);
                const float4 h0 = hhr[0], h1 = hhr[1];
                float2 a2 = ffma2(mf2(h0.x, h0.y), aw2r[0], mf2(ab2d, 0.f));
                float2 a3 = ffma2(mf2(h0.z, h0.w), aw2r[1], mf2(0.f, 0.f));
                a2 = ffma2(mf2(h1.x, h1.y), aw2r[2], a2);
                a3 = ffma2(mf2(h1.z, h1.w), aw2r[3], a3);

                const float4* phr = reinterpret_cast<const float4*>(s_ph + row * 8);
                const float4 p0 = phr[0], p1 = phr[1];
                float2 pv = ffma2(mf2(p0.x, p0.y), pw2r[0], mf2(pb2d, 0.f));
                float2 pw = ffma2(mf2(p0.z, p0.w), pw2r[1], mf2(0.f, 0.f));
                pv = ffma2(mf2(p1.x, p1.y), pw2r[2], pv);
                pw = ffma2(mf2(p1.z, p1.w), pw2r[3], pw);

                float2 va = mf2(sd, 0.f), vb = mf2(0.f, 0.f);
                float2 vc = mf2(0.f, 0.f), vd = mf2(0.f, 0.f);
                const float4* kr4 = reinterpret_cast<const float4*>(&s_k[bb][row * 68]);
                #pragma unroll
                for (int c4 = 0; c4 < 16; c4 += 2) {
                    const float4 k0 = kr4[c4], k1 = kr4[c4 + 1];
                    va = ffma2(mf2(k0.x, k0.y), wv2[2 * c4],     va);
                    vb = ffma2(mf2(k0.z, k0.w), wv2[2 * c4 + 1], vb);
                    vc = ffma2(mf2(k1.x, k1.y), wv2[2 * c4 + 2], vc);
                    vd = ffma2(mf2(k1.z, k1.w), wv2[2 * c4 + 3], vd);
                }
                const float vh = ((va.x + vb.x) + (vc.x + vd.x))
                               + ((va.y + vb.y) + (vc.y + vd.y));
                logit[v] = ((mbits >> v) & 1) ? ((a2.x + a3.x) + (a2.y + a3.y)) : -1e9f;
                val[v] = vh + (pv.x + pw.x) + (pv.y + pw.y);
            }
            // parallel max tree
            float m0 = fmaxf(fmaxf(logit[0], logit[1]), fmaxf(logit[2], logit[3]));
            float m1 = fmaxf(fmaxf(logit[4], logit[5]), fmaxf(logit[6], logit[7]));
            const float m = fmaxf(m0, m1);
            // 8 independent exps
            float ev[8];
            #pragma unroll
            for (int v = 0; v < 8; ++v) ev[v] = __expf(logit[v] - m);
            float ssum = ((ev[0] + ev[1]) + (ev[2] + ev[3])) + ((ev[4] + ev[5]) + (ev[6] + ev[7]));
            float wacc = ((ev[0] * val[0] + ev[1] * val[1]) + (ev[2] * val[2] + ev[3] * val[3]))
                       + ((ev[4] * val[4] + ev[5] * val[5]) + (ev[6] * val[6] + ev[7] * val[7]));
            s_x[ln * 64 + d] = __fdividef(wacc, ssum);
        }
        __syncthreads();

        // ---- output GEMM: y = x @ out_w + out_b  ([c][d] layout, conflict-free) ----
        {
            float acc0 = obd, acc1 = 0.f, acc2 = 0.f, acc3 = 0.f;
            const float4* xr = reinterpret_cast<const float4*>(s_x + ln * 64);
            const float* wc = s_ow + d;
            #pragma unroll
            for (int c4 = 0; c4 < 16; ++c4) {
                const float4 xx = xr[c4];
                acc0 += xx.x * wc[(4 * c4 + 0) * 64];
                acc1 += xx.y * wc[(4 * c4 + 1) * 64];
                acc2 += xx.z * wc[(4 * c4 + 2) * 64];
                acc3 += xx.w * wc[(4 * c4 + 3) * 64];
            }
            out[(base_n + ln) * 64 + d] = (acc0 + acc1) + (acc2 + acc3);
        }
        // no trailing sync: next iteration's CPWAIT0+__syncthreads orders everything
    }
}

extern "C" void kernel_launch(void* const* d_in, const int* in_sizes, int n_in,
                              void* d_out, int out_size)
{
    const float* q        = (const float*)d_in[0];
    const float* k        = (const float*)d_in[1];
    const float* pos      = (const float*)d_in[2];
    const float* strength = (const float*)d_in[3];
    const float* q_tbl    = (const float*)d_in[4];
    const float* k_tbl    = (const float*)d_in[5];
    const float* v_tbl    = (const float*)d_in[6];
    const float* pos_w1   = (const float*)d_in[7];
    const float* pos_b1   = (const float*)d_in[8];
    const float* pos_w2   = (const float*)d_in[9];
    const float* pos_b2   = (const float*)d_in[10];
    const float* attn_w1  = (const float*)d_in[11];
    const float* attn_b1  = (const float*)d_in[12];
    const float* attn_w2  = (const float*)d_in[13];
    const float* attn_b2  = (const float*)d_in[14];
    const float* out_w    = (const float*)d_in[15];
    const float* out_b    = (const float*)d_in[16];
    const float* str_w    = (const float*)d_in[17];
    const float* str_b    = (const float*)d_in[18];
    const int*   mask     = (const int*)d_in[19];
    const int*   embed_id = (const int*)d_in[20];
    float* out = (float*)d_out;

    precompute_kernel<<<1, 256>>>(strength, str_w, str_b, q_tbl, k_tbl,
                                  attn_w1, attn_b1, pos_w2, pos_b2, embed_id);

    dim3 grid(BQ, 2);
    attn_main<<<grid, 256>>>(q, k, pos, v_tbl,
                             pos_w1, pos_b1, pos_w2, pos_b2,
                             attn_w2, attn_b2, out_w, out_b,
                             mask, embed_id, out);
}